// round 3
// baseline (speedup 1.0000x reference)
#include <cuda_runtime.h>
#include <cuda_bf16.h>

// CropAndResize: image (8,256,100,152) f32, boxes (1000,4) f32 [y1,x1,y2,x2],
// box_ind (1000,) i32 -> out (1000,256,14,14) f32.
//
// One block per (n, y) output row. Coordinate math (depends only on (n,y) and
// (n,x), never on channel) computed once into smem and amortized over
// 256 channels x 14 x. Thread = (x lane 0..15, channel-group of 8); inner loop
// fully unrolled: 4 LDG + 4 FFMA + 1 STG per element, ~32 outstanding loads
// per warp. Validity folded into the 4 bilinear weights (extrapolation value
// is 0) -> zero branches. Output stored with streaming hint (__stcs) so the
// write-once output doesn't evict the ~L2-resident image (124.6 MB vs 126 MB L2).

#define IMG_B   8
#define IMG_C   256
#define IMG_H   100
#define IMG_W   152
#define CROP    14
#define NBOX    1000
#define CPT     8      // channels per thread
#define BLOCKT  512    // 16 x-lanes * 32 channel-groups
#define PLANE   (IMG_H * IMG_W)

__global__ __launch_bounds__(BLOCKT)
void crop_resize_kernel(const float* __restrict__ image,
                        const float* __restrict__ boxes,
                        const int*   __restrict__ box_ind,
                        float*       __restrict__ out)
{
    __shared__ int   s_li[16], s_ri[16];
    __shared__ float s_xw[16], s_vx[16];
    __shared__ int   s_rowt, s_rowb, s_b;
    __shared__ float s_yw, s_vy;

    const int y = blockIdx.x;   // 0..13
    const int n = blockIdx.y;   // 0..999

    const int tx = threadIdx.x & 15;   // x lane (0..15; 14..15 idle in loop)
    const int ty = threadIdx.x >> 4;   // channel group (0..31)

    if (threadIdx.x < 16) {
        const int x = threadIdx.x;
        const float y1 = boxes[n * 4 + 0];
        const float x1 = boxes[n * 4 + 1];
        const float y2 = boxes[n * 4 + 2];
        const float x2 = boxes[n * 4 + 3];

        // x taps (depend only on (n, x))
        float ws   = (x2 - x1) * (float)(IMG_W - 1) / (float)(CROP - 1);
        float in_x = fmaf((float)x, ws, x1 * (float)(IMG_W - 1));
        float vx   = (in_x >= 0.0f && in_x <= (float)(IMG_W - 1)) ? 1.0f : 0.0f;
        float left = floorf(in_x);
        float lc   = fminf(fmaxf(left,        0.0f), (float)(IMG_W - 1));
        float rc   = fminf(fmaxf(left + 1.0f, 0.0f), (float)(IMG_W - 1));
        s_xw[x] = in_x - left;
        s_vx[x] = vx;
        s_li[x] = (int)lc;
        s_ri[x] = (int)rc;

        if (x == 0) {
            // y taps (depend only on (n, y))
            float hs   = (y2 - y1) * (float)(IMG_H - 1) / (float)(CROP - 1);
            float in_y = fmaf((float)y, hs, y1 * (float)(IMG_H - 1));
            float vy   = (in_y >= 0.0f && in_y <= (float)(IMG_H - 1)) ? 1.0f : 0.0f;
            float top  = floorf(in_y);
            float tc   = fminf(fmaxf(top,        0.0f), (float)(IMG_H - 1));
            float bc   = fminf(fmaxf(top + 1.0f, 0.0f), (float)(IMG_H - 1));
            s_yw   = in_y - top;
            s_vy   = vy;
            s_rowt = (int)tc * IMG_W;
            s_rowb = (int)bc * IMG_W;
            s_b    = box_ind[n];
        }
    }
    __syncthreads();

    if (tx >= CROP) return;

    const float xw = s_xw[tx];
    const float yw = s_yw;
    const float v  = s_vx[tx] * s_vy;  // validity folded into weights (extrap value = 0)

    // 4 bilinear weights, pre-scaled by validity.
    const float w_tr = xw * (1.0f - yw) * v;
    const float w_tl = (1.0f - yw) * v - w_tr;
    const float w_br = xw * yw * v;
    const float w_bl = yw * v - w_br;

    const int o_tl = s_rowt + s_li[tx];
    const int o_tr = s_rowt + s_ri[tx];
    const int o_bl = s_rowb + s_li[tx];
    const int o_br = s_rowb + s_ri[tx];

    const int c0 = ty * CPT;
    const float* p  = image + ((size_t)s_b * IMG_C + c0) * PLANE;
    float*       po = out   + (((size_t)n * IMG_C + c0) * CROP + y) * CROP + tx;

#pragma unroll
    for (int i = 0; i < CPT; ++i) {
        float tl = __ldg(p + o_tl);
        float tr = __ldg(p + o_tr);
        float bl = __ldg(p + o_bl);
        float br = __ldg(p + o_br);
        float val = fmaf(tl, w_tl, fmaf(tr, w_tr, fmaf(bl, w_bl, br * w_br)));
        __stcs(po, val);   // streaming store: don't pollute L2
        p  += PLANE;
        po += CROP * CROP;
    }
}

extern "C" void kernel_launch(void* const* d_in, const int* in_sizes, int n_in,
                              void* d_out, int out_size)
{
    const float* image   = (const float*)d_in[0];
    const float* boxes   = (const float*)d_in[1];
    const int*   box_ind = (const int*)d_in[2];
    float*       out     = (float*)d_out;

    dim3 grid(CROP, NBOX);   // (y, n)
    crop_resize_kernel<<<grid, BLOCKT>>>(image, boxes, box_ind, out);
}

// round 4
// speedup vs baseline: 1.0004x; 1.0004x over previous
#include <cuda_runtime.h>
#include <cuda_bf16.h>

// CropAndResize: image (8,256,100,152) f32, boxes (1000,4) f32 [y1,x1,y2,x2],
// box_ind (1000,) i32 -> out (1000,256,14,14) f32.
//
// R3 insight (ncu): DRAM=70.2% -> 890 MB moved vs 325 MB floor. Boxes in
// original order interleave all 8 images per scheduling wave, thrashing L2.
// Fix: kernel 1 = deterministic stable counting sort of boxes by box_ind
// (perm in __device__ global); kernel 2 processes boxes in image-grouped
// order, so each wave's working set is ~one image (15.6 MB, L2-resident).
//
// Main kernel: one block per (perm slot, y). Coordinate math once per block
// in smem; thread = (x lane, channel-group of 8); inner loop = 4 LDG +
// 4 FFMA + 1 streaming STG per element, validity folded into weights.

#define IMG_B   8
#define IMG_C   256
#define IMG_H   100
#define IMG_W   152
#define CROP    14
#define NBOX    1000
#define CPT     8      // channels per thread
#define BLOCKT  512    // 16 x-lanes * 32 channel-groups
#define PLANE   (IMG_H * IMG_W)

__device__ int d_perm[NBOX];

// Deterministic stable counting sort of box indices by image id.
// One block, 256 threads. Phases: parallel smem load -> 8-thread bin count
// (smem broadcast reads) -> serial exclusive scan (8 bins) -> 8-thread stable
// scatter. ~5 us total.
__global__ void sort_boxes_kernel(const int* __restrict__ box_ind)
{
    __shared__ int s_ind[NBOX];
    __shared__ int s_start[IMG_B];

    const int tid = threadIdx.x;

    for (int i = tid; i < NBOX; i += blockDim.x)
        s_ind[i] = box_ind[i];
    __syncthreads();

    if (tid < IMG_B) {
        int cnt = 0;
#pragma unroll 8
        for (int i = 0; i < NBOX; ++i)
            cnt += (s_ind[i] == tid) ? 1 : 0;
        s_start[tid] = cnt;
    }
    __syncthreads();

    if (tid == 0) {
        int acc = 0;
#pragma unroll
        for (int b = 0; b < IMG_B; ++b) {
            int c = s_start[b];
            s_start[b] = acc;
            acc += c;
        }
    }
    __syncthreads();

    if (tid < IMG_B) {
        int pos = s_start[tid];
        for (int i = 0; i < NBOX; ++i) {
            if (s_ind[i] == tid)
                d_perm[pos++] = i;
        }
    }
}

__global__ __launch_bounds__(BLOCKT)
void crop_resize_kernel(const float* __restrict__ image,
                        const float* __restrict__ boxes,
                        const int*   __restrict__ box_ind,
                        float*       __restrict__ out)
{
    __shared__ int   s_li[16], s_ri[16];
    __shared__ float s_xw[16], s_vx[16];
    __shared__ int   s_rowt, s_rowb, s_b, s_n;
    __shared__ float s_yw, s_vy;

    const int y = blockIdx.x;   // 0..13

    const int tx = threadIdx.x & 15;   // x lane (0..15; 14..15 idle in loop)
    const int ty = threadIdx.x >> 4;   // channel group (0..31)

    if (threadIdx.x < 16) {
        const int x = threadIdx.x;
        const int n = d_perm[blockIdx.y];   // image-grouped box order
        const float y1 = boxes[n * 4 + 0];
        const float x1 = boxes[n * 4 + 1];
        const float y2 = boxes[n * 4 + 2];
        const float x2 = boxes[n * 4 + 3];

        // x taps (depend only on (n, x))
        float ws   = (x2 - x1) * (float)(IMG_W - 1) / (float)(CROP - 1);
        float in_x = fmaf((float)x, ws, x1 * (float)(IMG_W - 1));
        float vx   = (in_x >= 0.0f && in_x <= (float)(IMG_W - 1)) ? 1.0f : 0.0f;
        float left = floorf(in_x);
        float lc   = fminf(fmaxf(left,        0.0f), (float)(IMG_W - 1));
        float rc   = fminf(fmaxf(left + 1.0f, 0.0f), (float)(IMG_W - 1));
        s_xw[x] = in_x - left;
        s_vx[x] = vx;
        s_li[x] = (int)lc;
        s_ri[x] = (int)rc;

        if (x == 0) {
            // y taps (depend only on (n, y))
            float hs   = (y2 - y1) * (float)(IMG_H - 1) / (float)(CROP - 1);
            float in_y = fmaf((float)y, hs, y1 * (float)(IMG_H - 1));
            float vy   = (in_y >= 0.0f && in_y <= (float)(IMG_H - 1)) ? 1.0f : 0.0f;
            float top  = floorf(in_y);
            float tc   = fminf(fmaxf(top,        0.0f), (float)(IMG_H - 1));
            float bc   = fminf(fmaxf(top + 1.0f, 0.0f), (float)(IMG_H - 1));
            s_yw   = in_y - top;
            s_vy   = vy;
            s_rowt = (int)tc * IMG_W;
            s_rowb = (int)bc * IMG_W;
            s_b    = box_ind[n];
            s_n    = n;
        }
    }
    __syncthreads();

    if (tx >= CROP) return;

    const float xw = s_xw[tx];
    const float yw = s_yw;
    const float v  = s_vx[tx] * s_vy;  // validity folded into weights (extrap value = 0)

    const float w_tr = xw * (1.0f - yw) * v;
    const float w_tl = (1.0f - yw) * v - w_tr;
    const float w_br = xw * yw * v;
    const float w_bl = yw * v - w_br;

    const int o_tl = s_rowt + s_li[tx];
    const int o_tr = s_rowt + s_ri[tx];
    const int o_bl = s_rowb + s_li[tx];
    const int o_br = s_rowb + s_ri[tx];

    const int c0 = ty * CPT;
    const float* p  = image + ((size_t)s_b * IMG_C + c0) * PLANE;
    float*       po = out   + (((size_t)s_n * IMG_C + c0) * CROP + y) * CROP + tx;

#pragma unroll
    for (int i = 0; i < CPT; ++i) {
        float tl = __ldg(p + o_tl);
        float tr = __ldg(p + o_tr);
        float bl = __ldg(p + o_bl);
        float br = __ldg(p + o_br);
        float val = fmaf(tl, w_tl, fmaf(tr, w_tr, fmaf(bl, w_bl, br * w_br)));
        __stcs(po, val);   // streaming store: don't pollute L2
        p  += PLANE;
        po += CROP * CROP;
    }
}

extern "C" void kernel_launch(void* const* d_in, const int* in_sizes, int n_in,
                              void* d_out, int out_size)
{
    const float* image   = (const float*)d_in[0];
    const float* boxes   = (const float*)d_in[1];
    const int*   box_ind = (const int*)d_in[2];
    float*       out     = (float*)d_out;

    sort_boxes_kernel<<<1, 256>>>(box_ind);

    dim3 grid(CROP, NBOX);   // (y, sorted box slot)
    crop_resize_kernel<<<grid, BLOCKT>>>(image, boxes, box_ind, out);
}

// round 9
// speedup vs baseline: 1.2011x; 1.2006x over previous
#include <cuda_runtime.h>
#include <cuda_bf16.h>

// CropAndResize: image (8,256,100,152) f32, boxes (1000,4) f32 [y1,x1,y2,x2],
// box_ind (1000,) i32 -> out (1000,256,14,14) f32.
//
// R4 insight: image-grouped box order fixed DRAM (70%->25%) but the serial
// counting sort cost ~21 us and ate the win; main kernel is L1-wavefront
// bound (L1=75%). Pending (unmeasured, broker timeouts R5-R8):
// (a) atomic-histogram sort (~3 us; non-stable within a bin, but each box
// writes a disjoint output slice so d_out is invariant to perm order),
// (b) 256-thread blocks with CPT=16 for more front-batched LDG MLP.

#define IMG_B   8
#define IMG_C   256
#define IMG_H   100
#define IMG_W   152
#define CROP    14
#define NBOX    1000
#define CPT     16     // channels per thread
#define BLOCKT  256    // 16 x-lanes * 16 channel-groups
#define PLANE   (IMG_H * IMG_W)

__device__ int d_perm[NBOX];

// Group boxes by image id: atomic histogram -> tiny scan -> atomic scatter.
// Non-stable within a bin (output-invariant). One block, 1024 threads.
__global__ void sort_boxes_kernel(const int* __restrict__ box_ind)
{
    __shared__ int s_cnt[IMG_B];
    __shared__ int s_base[IMG_B];

    const int tid = threadIdx.x;
    const bool active = (tid < NBOX);

    if (tid < IMG_B) s_cnt[tid] = 0;
    __syncthreads();

    int b = 0;
    if (active) {
        b = box_ind[tid];
        atomicAdd(&s_cnt[b], 1);
    }
    __syncthreads();

    if (tid == 0) {
        int acc = 0;
#pragma unroll
        for (int i = 0; i < IMG_B; ++i) {
            s_base[i] = acc;
            acc += s_cnt[i];
        }
    }
    __syncthreads();

    if (active) {
        int pos = atomicAdd(&s_base[b], 1);
        d_perm[pos] = tid;
    }
}

__global__ __launch_bounds__(BLOCKT)
void crop_resize_kernel(const float* __restrict__ image,
                        const float* __restrict__ boxes,
                        const int*   __restrict__ box_ind,
                        float*       __restrict__ out)
{
    __shared__ int   s_li[16], s_ri[16];
    __shared__ float s_xw[16], s_vx[16];
    __shared__ int   s_rowt, s_rowb, s_b, s_n;
    __shared__ float s_yw, s_vy;

    const int y = blockIdx.x;   // 0..13

    const int tx = threadIdx.x & 15;   // x lane (0..15; 14..15 idle in loop)
    const int ty = threadIdx.x >> 4;   // channel group (0..15)

    if (threadIdx.x < 16) {
        const int x = threadIdx.x;
        const int n = d_perm[blockIdx.y];   // image-grouped box order
        const float y1 = boxes[n * 4 + 0];
        const float x1 = boxes[n * 4 + 1];
        const float y2 = boxes[n * 4 + 2];
        const float x2 = boxes[n * 4 + 3];

        // x taps (depend only on (n, x))
        float ws   = (x2 - x1) * (float)(IMG_W - 1) / (float)(CROP - 1);
        float in_x = fmaf((float)x, ws, x1 * (float)(IMG_W - 1));
        float vx   = (in_x >= 0.0f && in_x <= (float)(IMG_W - 1)) ? 1.0f : 0.0f;
        float left = floorf(in_x);
        float lc   = fminf(fmaxf(left,        0.0f), (float)(IMG_W - 1));
        float rc   = fminf(fmaxf(left + 1.0f, 0.0f), (float)(IMG_W - 1));
        s_xw[x] = in_x - left;
        s_vx[x] = vx;
        s_li[x] = (int)lc;
        s_ri[x] = (int)rc;

        if (x == 0) {
            // y taps (depend only on (n, y))
            float hs   = (y2 - y1) * (float)(IMG_H - 1) / (float)(CROP - 1);
            float in_y = fmaf((float)y, hs, y1 * (float)(IMG_H - 1));
            float vy   = (in_y >= 0.0f && in_y <= (float)(IMG_H - 1)) ? 1.0f : 0.0f;
            float top  = floorf(in_y);
            float tc   = fminf(fmaxf(top,        0.0f), (float)(IMG_H - 1));
            float bc   = fminf(fmaxf(top + 1.0f, 0.0f), (float)(IMG_H - 1));
            s_yw   = in_y - top;
            s_vy   = vy;
            s_rowt = (int)tc * IMG_W;
            s_rowb = (int)bc * IMG_W;
            s_b    = box_ind[n];
            s_n    = n;
        }
    }
    __syncthreads();

    if (tx >= CROP) return;

    const float xw = s_xw[tx];
    const float yw = s_yw;
    const float v  = s_vx[tx] * s_vy;  // validity folded into weights (extrap value = 0)

    const float w_tr = xw * (1.0f - yw) * v;
    const float w_tl = (1.0f - yw) * v - w_tr;
    const float w_br = xw * yw * v;
    const float w_bl = yw * v - w_br;

    const int o_tl = s_rowt + s_li[tx];
    const int o_tr = s_rowt + s_ri[tx];
    const int o_bl = s_rowb + s_li[tx];
    const int o_br = s_rowb + s_ri[tx];

    const int c0 = ty * CPT;
    const float* p  = image + ((size_t)s_b * IMG_C + c0) * PLANE;
    float*       po = out   + (((size_t)s_n * IMG_C + c0) * CROP + y) * CROP + tx;

#pragma unroll
    for (int i = 0; i < CPT; ++i) {
        float tl = __ldg(p + o_tl);
        float tr = __ldg(p + o_tr);
        float bl = __ldg(p + o_bl);
        float br = __ldg(p + o_br);
        float val = fmaf(tl, w_tl, fmaf(tr, w_tr, fmaf(bl, w_bl, br * w_br)));
        __stcs(po, val);   // streaming store: don't pollute L2
        p  += PLANE;
        po += CROP * CROP;
    }
}

extern "C" void kernel_launch(void* const* d_in, const int* in_sizes, int n_in,
                              void* d_out, int out_size)
{
    const float* image   = (const float*)d_in[0];
    const float* boxes   = (const float*)d_in[1];
    const int*   box_ind = (const int*)d_in[2];
    float*       out     = (float*)d_out;

    sort_boxes_kernel<<<1, 1024>>>(box_ind);

    dim3 grid(CROP, NBOX);   // (y, sorted box slot)
    crop_resize_kernel<<<grid, BLOCKT>>>(image, boxes, box_ind, out);
}

// round 15
// speedup vs baseline: 1.3196x; 1.0987x over previous
#include <cuda_runtime.h>
#include <cuda_bf16.h>

// CropAndResize: image (8,256,100,152) f32, boxes (1000,4) f32 [y1,x1,y2,x2],
// box_ind (1000,) i32 -> out (1000,256,14,14) f32.
//
// R9 state: sort fixed (4us), main kernel 129.7us, L1=79.9% binding.
// Pending change (unmeasured, broker timeouts R10-R14): merge the tl/tr (and
// bl/br) tap loads. ri = li+1 always, so the 2nd tap re-touches the same 128B
// lines as the 1st but from a separate LDG (separate wavefronts). Warp layout:
// lanes 0-13 load li columns, lanes 14-27 load ri columns of the SAME channel
// row -> one LDG serves both taps over the same ~2.5-line span.
// __shfl_down_sync(14) delivers the right tap to the output lanes.
// 2 LDG + 1 STG per channel instead of 4 + 1: ~1.75x fewer L1 wavefronts;
// L2 becomes the wall.

#define IMG_B   8
#define IMG_C   256
#define IMG_H   100
#define IMG_W   152
#define CROP    14
#define NBOX    1000
#define BLOCKT  256    // 8 warps; each warp owns 32 consecutive channels
#define PLANE   (IMG_H * IMG_W)

__device__ int d_perm[NBOX];

// Group boxes by image id: atomic histogram -> tiny scan -> atomic scatter.
// Non-stable within a bin (output-invariant: each box owns a disjoint out slice).
__global__ void sort_boxes_kernel(const int* __restrict__ box_ind)
{
    __shared__ int s_cnt[IMG_B];
    __shared__ int s_base[IMG_B];

    const int tid = threadIdx.x;
    const bool active = (tid < NBOX);

    if (tid < IMG_B) s_cnt[tid] = 0;
    __syncthreads();

    int b = 0;
    if (active) {
        b = box_ind[tid];
        atomicAdd(&s_cnt[b], 1);
    }
    __syncthreads();

    if (tid == 0) {
        int acc = 0;
#pragma unroll
        for (int i = 0; i < IMG_B; ++i) {
            s_base[i] = acc;
            acc += s_cnt[i];
        }
    }
    __syncthreads();

    if (active) {
        int pos = atomicAdd(&s_base[b], 1);
        d_perm[pos] = tid;
    }
}

__global__ __launch_bounds__(BLOCKT)
void crop_resize_kernel(const float* __restrict__ image,
                        const float* __restrict__ boxes,
                        const int*   __restrict__ box_ind,
                        float*       __restrict__ out)
{
    __shared__ int   s_li[16], s_ri[16];
    __shared__ float s_xw[16], s_vx[16];
    __shared__ int   s_rowt, s_rowb, s_b, s_n;
    __shared__ float s_yw, s_vy;

    const int y = blockIdx.x;   // 0..13

    if (threadIdx.x < 16) {
        const int x = threadIdx.x;
        const int n = d_perm[blockIdx.y];   // image-grouped box order
        const float y1 = boxes[n * 4 + 0];
        const float x1 = boxes[n * 4 + 1];
        const float y2 = boxes[n * 4 + 2];
        const float x2 = boxes[n * 4 + 3];

        // x taps (depend only on (n, x))
        float ws   = (x2 - x1) * (float)(IMG_W - 1) / (float)(CROP - 1);
        float in_x = fmaf((float)x, ws, x1 * (float)(IMG_W - 1));
        float vx   = (in_x >= 0.0f && in_x <= (float)(IMG_W - 1)) ? 1.0f : 0.0f;
        float left = floorf(in_x);
        float lc   = fminf(fmaxf(left,        0.0f), (float)(IMG_W - 1));
        float rc   = fminf(fmaxf(left + 1.0f, 0.0f), (float)(IMG_W - 1));
        s_xw[x] = in_x - left;
        s_vx[x] = vx;
        s_li[x] = (int)lc;
        s_ri[x] = (int)rc;

        if (x == 0) {
            // y taps (depend only on (n, y))
            float hs   = (y2 - y1) * (float)(IMG_H - 1) / (float)(CROP - 1);
            float in_y = fmaf((float)y, hs, y1 * (float)(IMG_H - 1));
            float vy   = (in_y >= 0.0f && in_y <= (float)(IMG_H - 1)) ? 1.0f : 0.0f;
            float top  = floorf(in_y);
            float tc   = fminf(fmaxf(top,        0.0f), (float)(IMG_H - 1));
            float bc   = fminf(fmaxf(top + 1.0f, 0.0f), (float)(IMG_H - 1));
            s_yw   = in_y - top;
            s_vy   = vy;
            s_rowt = (int)tc * IMG_W;
            s_rowb = (int)bc * IMG_W;
            s_b    = box_ind[n];
            s_n    = n;
        }
    }
    __syncthreads();

    const int lane = threadIdx.x & 31;
    const int wid  = threadIdx.x >> 5;   // 0..7: each warp owns 32 channels

    // Lane -> column mapping: 0-13 = left taps, 14-27 = right taps, 28-31 dummy.
    const int  xi   = (lane < 14) ? lane : ((lane < 28) ? (lane - 14) : 0);
    const int  col  = (lane < 14) ? s_li[xi] : s_ri[xi];
    const int  o_t  = s_rowt + col;
    const int  o_b  = s_rowb + col;

    const float xw = s_xw[xi];
    const float yw = s_yw;
    const float v  = s_vx[xi] * s_vy;   // validity (extrap value = 0)

    const int cbase = wid * 32;
    const float* p  = image + ((size_t)s_b * IMG_C + cbase) * PLANE;
    float*       po = out   + (((size_t)s_n * IMG_C + cbase) * CROP + y) * CROP + lane;
    const bool   wr = (lane < CROP);

#pragma unroll 4
    for (int ch = 0; ch < 32; ++ch) {
        float vt = __ldg(p + o_t);            // one LDG: tl (lanes 0-13) + tr (14-27)
        float vb = __ldg(p + o_b);            // one LDG: bl + br
        float trv = __shfl_down_sync(0xFFFFFFFFu, vt, 14);
        float brv = __shfl_down_sync(0xFFFFFFFFu, vb, 14);
        float top = fmaf(trv - vt, xw, vt);   // horizontal lerp
        float bot = fmaf(brv - vb, xw, vb);
        float val = fmaf(bot - top, yw, top) * v;
        if (wr) __stcs(po, val);              // streaming store: don't pollute L2
        p  += PLANE;
        po += CROP * CROP;
    }
}

extern "C" void kernel_launch(void* const* d_in, const int* in_sizes, int n_in,
                              void* d_out, int out_size)
{
    const float* image   = (const float*)d_in[0];
    const float* boxes   = (const float*)d_in[1];
    const int*   box_ind = (const int*)d_in[2];
    float*       out     = (float*)d_out;

    sort_boxes_kernel<<<1, 1024>>>(box_ind);

    dim3 grid(CROP, NBOX);   // (y, sorted box slot)
    crop_resize_kernel<<<grid, BLOCKT>>>(image, boxes, box_ind, out);
}